// round 11
// baseline (speedup 1.0000x reference)
#include <cuda_runtime.h>
#include <cstdint>

#define AN 13824          // 24*24*24 anchors
#define TK 60             // TOPK
#define NMSK 20           // NMS_TOPK
#define CAP 512           // per-batch candidate capacity
#define NB 256            // batches
#define SCTA 4            // scan CTAs per batch
#define SNT 128           // scan threads per CTA
#define F4B 864           // float4s per scan CTA (3456/4)
#define THRF 2.25f        // fixed fast-path threshold: P(x>=2.25)=.0122 -> ~169+-13 per batch

__device__ unsigned long long g_cand[NB * CAP];
__device__ int g_cnt[NB];   // zero-initialized; re-zeroed by nms kernel each call

__device__ __forceinline__ unsigned int fkey(float x) {
    unsigned int b = __float_as_uint(x);
    return (b & 0x80000000u) ? ~b : (b | 0x80000000u);
}
__device__ __forceinline__ float fkey_inv(unsigned int u) {
    unsigned int b = (u & 0x80000000u) ? (u & 0x7fffffffu) : ~u;
    return __uint_as_float(b);
}
__device__ __forceinline__ void push_cand(int b, float v, int idx) {
    int pos = atomicAdd(&g_cnt[b], 1);
    if (pos < CAP)
        g_cand[b * CAP + pos] = ((unsigned long long)fkey(v) << 14) |
                                (unsigned long long)(16383 - idx);
}

// ---------------- Kernel 1: streaming scan + threshold push ----------------
// No smem, no barriers, ~25 regs: all 7 LDG.128 front-batched for max MLP.
__global__ __launch_bounds__(SNT)
void scan_kernel(const float* __restrict__ cls)
{
    const int blk = blockIdx.x;
    const int b   = blk >> 2;
    const int p   = blk & 3;
    const int t   = threadIdx.x;
    const float4* cb4 = (const float4*)(cls + (size_t)b * AN) + p * F4B;

#pragma unroll
    for (int j = 0; j < 7; j++) {
        int i = t + SNT * j;
        if (i < F4B) {
            float4 v = __ldg(&cb4[i]);
            int base = 4 * (p * F4B + i);
            if (v.x >= THRF) push_cand(b, v.x, base + 0);
            if (v.y >= THRF) push_cand(b, v.y, base + 1);
            if (v.z >= THRF) push_cand(b, v.z, base + 2);
            if (v.w >= THRF) push_cand(b, v.w, base + 3);
        }
    }
}

// ---------------- Kernel 2: rank + gather(cand only) + IoU20 + NMS + out ----------------
__global__ __launch_bounds__(128, 8)
void nms_kernel(const float* __restrict__ cls,
                const float* __restrict__ shp,
                const float* __restrict__ off,
                float* __restrict__ out)
{
    const int b    = blockIdx.x;
    const int t    = threadIdx.x;
    const int lane = t & 31;
    const int wid  = t >> 5;

    __shared__ unsigned long long s_cand[CAP];
    __shared__ unsigned long long s_key[TK];
    __shared__ float s_sc[TK];
    __shared__ int   s_idx[TK];
    __shared__ unsigned int s_valid[2];
    __shared__ int   s_crow[NMSK];
    __shared__ float s_gv[6][NMSK];
    __shared__ float s_ctr[NMSK][3], s_sz[NMSK][3];
    __shared__ float s_lo[NMSK][3], s_hi[NMSK][3], s_vol[NMSK];
    __shared__ unsigned int s_m[NMSK];
    __shared__ unsigned int s_kept;
    __shared__ int   s_red[4];
    __shared__ int   s_nc2;

    int C = g_cnt[b];

    if (C >= TK && C <= CAP) {
        // fast path: copy candidates to smem
        for (int i = t; i < C; i += 128)
            s_cand[i] = g_cand[b * CAP + i];
        __syncthreads();
    } else {
        // exact fallback (never taken for N(0,1) data): 50-bit key descent.
        const float* cb = cls + (size_t)b * AN;
        unsigned long long cutk = 0;
        for (int bit = 49; bit >= 0; bit--) {
            unsigned long long c2 = cutk | (1ull << bit);
            int cc = 0;
            for (int i = t; i < AN; i += 128) {
                unsigned long long k = ((unsigned long long)fkey(cb[i]) << 14) |
                                       (unsigned long long)(16383 - i);
                cc += (k >= c2);
            }
            cc = __reduce_add_sync(0xffffffffu, (unsigned int)cc);
            if (lane == 0) s_red[wid] = cc;
            __syncthreads();
            int tot = s_red[0] + s_red[1] + s_red[2] + s_red[3];
            if (tot >= TK) cutk = c2;
            __syncthreads();
        }
        // keys unique -> exactly TK keys >= cutk
        if (t == 0) s_nc2 = 0;
        __syncthreads();
        for (int i = t; i < AN; i += 128) {
            unsigned long long k = ((unsigned long long)fkey(cb[i]) << 14) |
                                   (unsigned long long)(16383 - i);
            if (k >= cutk) {
                int pos = atomicAdd(&s_nc2, 1);
                if (pos < TK) s_cand[pos] = k;
            }
        }
        __syncthreads();
        C = TK;
    }

    // exact ranking -> s_key[0..59] (descending)
    for (int c = t; c < C; c += 128) {
        unsigned long long k = s_cand[c];
        int r = 0;
        for (int m = 0; m < C; m++)
            r += (s_cand[m] > k);
        if (r < TK) s_key[r] = k;
    }
    __syncthreads();

    // scores / indices / valid ballot
    float sc = 0.0f;
    if (t < TK) {
        unsigned long long k = s_key[t];
        float logit = fkey_inv((unsigned int)(k >> 14));
        sc = 1.0f / (1.0f + expf(-logit));
        s_sc[t]  = sc;
        s_idx[t] = 16383 - (int)(k & 16383ull);
    }
    {
        unsigned int vb = __ballot_sync(0xffffffffu, (t < TK) && (sc > 0.15f));
        if (wid < 2 && lane == 0) s_valid[wid] = vb;
    }
    __syncthreads();

    unsigned long long valid = ((unsigned long long)s_valid[1] << 32) | s_valid[0];
    int nc = __popcll(valid);
    if (nc > NMSK) nc = NMSK;

    // cand rows: first nc valid rows (rank order); parallel via popcount
    if (t < TK) {
        if ((valid >> t) & 1ull) {
            int rv = __popcll(valid & ((1ull << t) - 1ull));
            if (rv < NMSK) s_crow[rv] = t;
        }
    }
    __syncthreads();

    // gather off/shp for cand rows only (nc*6 <= 120 loads, all in flight)
    if (t < 6 * NMSK) {
        int ci = t / 6, comp = t - ci * 6;
        if (ci < nc) {
            int idx = s_idx[s_crow[ci]];
            size_t base = (size_t)b * 3 * AN;
            const float* src = (comp < 3) ? (off + base + (size_t)comp * AN)
                                          : (shp + base + (size_t)(comp - 3) * AN);
            s_gv[comp][ci] = __ldg(&src[idx]);
        }
    }
    __syncthreads();

    // box build for cand rows
    if (t < nc) {
        int idx = s_idx[s_crow[t]];
        int z   = idx / 576;
        int rem = idx - z * 576;
        int y   = rem / 24;
        int x   = rem - y * 24;
        float cz = ((float)z + s_gv[0][t]) * 4.0f;   // stride = 96/24 = 4
        float cy = ((float)y + s_gv[1][t]) * 4.0f;
        float cx = ((float)x + s_gv[2][t]) * 4.0f;
        float dz = 2.0f * s_gv[3][t];
        float dy = 2.0f * s_gv[4][t];
        float dx = 2.0f * s_gv[5][t];
        s_ctr[t][0] = cz; s_ctr[t][1] = cy; s_ctr[t][2] = cx;
        s_sz[t][0] = dz;  s_sz[t][1] = dy;  s_sz[t][2] = dx;
        s_lo[t][0] = cz - dz * 0.5f; s_lo[t][1] = cy - dy * 0.5f; s_lo[t][2] = cx - dx * 0.5f;
        s_hi[t][0] = cz + dz * 0.5f; s_hi[t][1] = cy + dy * 0.5f; s_hi[t][2] = cx + dx * 0.5f;
        s_vol[t] = dz * dy * dx;
    }
    __syncthreads();

    // IoU bitmask among cand rows (<=20x20)
    if (t < nc) {
        float l0 = s_lo[t][0], l1 = s_lo[t][1], l2 = s_lo[t][2];
        float h0 = s_hi[t][0], h1 = s_hi[t][1], h2 = s_hi[t][2];
        float vi = s_vol[t];
        unsigned int m = 0;
        for (int j = 0; j < nc; j++) {
            float iz = fminf(h0, s_hi[j][0]) - fmaxf(l0, s_lo[j][0]);
            float iy = fminf(h1, s_hi[j][1]) - fmaxf(l1, s_lo[j][1]);
            float ix = fminf(h2, s_hi[j][2]) - fmaxf(l2, s_lo[j][2]);
            float inter = fmaxf(iz, 0.0f) * fmaxf(iy, 0.0f) * fmaxf(ix, 0.0f);
            float uni = vi + s_vol[j] - inter;
            float iou = inter / fmaxf(uni, 1e-8f);
            unsigned int hit = (iou > 0.05f) && (j != t);
            m |= hit << j;
        }
        s_m[t] = m;
    }
    __syncthreads();

    // serial NMS over cand rows (cand = valid & rank<20 already encoded by nc)
    if (t == 0) {
        unsigned int supp = 0, kept = 0;
        for (int ci = 0; ci < nc; ci++) {
            unsigned int keep = !((supp >> ci) & 1u);
            kept |= keep << ci;
            if (keep) supp |= s_m[ci];
        }
        s_kept = kept;
        g_cnt[b] = 0;   // reset for next graph replay
    }
    __syncthreads();

    // output: kept rows (rank order) first, -1 padding
    float* ob = out + (size_t)b * TK * 8;
    if (t < TK) {
        unsigned int kept = s_kept;
        int nk = __popc(kept);
        if (t < nk) {
            // t-th set bit of kept
            int ci = -1, c2 = t;
            for (int q = 0; q < NMSK; q++) {
                if ((kept >> q) & 1u) {
                    if (c2 == 0) { ci = q; break; }
                    c2--;
                }
            }
            int row = s_crow[ci];
            float4* o4 = (float4*)(ob + t * 8);
            o4[0] = make_float4(1.0f, s_sc[row], s_ctr[ci][0], s_ctr[ci][1]);
            o4[1] = make_float4(s_ctr[ci][2], s_sz[ci][0], s_sz[ci][1], s_sz[ci][2]);
        } else {
            float4* o4 = (float4*)(ob + t * 8);
            o4[0] = make_float4(-1.0f, -1.0f, -1.0f, -1.0f);
            o4[1] = make_float4(-1.0f, -1.0f, -1.0f, -1.0f);
        }
    }
}

extern "C" void kernel_launch(void* const* d_in, const int* in_sizes, int n_in,
                              void* d_out, int out_size)
{
    const float* cls = (const float*)d_in[0];
    const float* shp = (const float*)d_in[1];
    const float* off = (const float*)d_in[2];
    float* out = (float*)d_out;
    scan_kernel<<<NB * SCTA, SNT>>>(cls);
    nms_kernel<<<NB, 128>>>(cls, shp, off, out);
}

// round 12
// speedup vs baseline: 1.8123x; 1.8123x over previous
#include <cuda_runtime.h>
#include <cstdint>

#define AN 13824          // 24*24*24 anchors
#define NT 512            // threads per block
#define NV 3456           // AN/4 float4s
#define TK 60             // TOPK
#define NMSK 20           // NMS_TOPK
#define CAP 512           // candidate capacity
#define NB 256            // batches
#define THRF 2.25f        // fast-path threshold: count ~169+-13 >= 60 at 8 sigma

__device__ __forceinline__ unsigned int fkey(float x) {
    unsigned int b = __float_as_uint(x);
    return (b & 0x80000000u) ? ~b : (b | 0x80000000u);
}
__device__ __forceinline__ float fkey_inv(unsigned int u) {
    unsigned int b = (u & 0x80000000u) ? (u & 0x7fffffffu) : ~u;
    return __uint_as_float(b);
}

__global__ __launch_bounds__(NT, 2)
void detect_fused_kernel(const float* __restrict__ cls,
                         const float* __restrict__ shp,
                         const float* __restrict__ off,
                         float* __restrict__ out)
{
    const int b    = blockIdx.x;
    const int t    = threadIdx.x;
    const int lane = t & 31;
    const int wid  = t >> 5;

    __shared__ unsigned long long s_cand[CAP];
    __shared__ int   s_ncand;
    __shared__ int   s_wcnt[2][16];
    __shared__ unsigned long long s_key[TK];
    __shared__ float s_sc[TK];
    __shared__ unsigned int s_valid[2];
    __shared__ int   s_crow[NMSK];
    __shared__ float s_gv[6][NMSK];
    __shared__ float s_ctr[NMSK][3], s_sz[NMSK][3];
    __shared__ float s_lo[NMSK][3], s_hi[NMSK][3], s_vol[NMSK];
    __shared__ unsigned int s_m[NMSK];
    __shared__ unsigned int s_kept;

    if (t == 0) s_ncand = 0;
    __syncthreads();

    // ---------------- Phase 1: stream cls, count + collect qualifiers ----------------
    // Slim loop: direct float compare; fkey only on ~169 qualifying elements.
    const float4* cb4 = (const float4*)(cls + (size_t)b * AN);
    int c = 0;
#pragma unroll
    for (int j = 0; j < 7; j++) {
        int i = t + NT * j;
        if (i < NV) {
            float4 v = __ldg(&cb4[i]);
            int base = 4 * i;
            if (v.x >= THRF) { c++; int p = atomicAdd(&s_ncand, 1); if (p < CAP)
                s_cand[p] = ((unsigned long long)fkey(v.x) << 14) | (unsigned long long)(16383 - (base + 0)); }
            if (v.y >= THRF) { c++; int p = atomicAdd(&s_ncand, 1); if (p < CAP)
                s_cand[p] = ((unsigned long long)fkey(v.y) << 14) | (unsigned long long)(16383 - (base + 1)); }
            if (v.z >= THRF) { c++; int p = atomicAdd(&s_ncand, 1); if (p < CAP)
                s_cand[p] = ((unsigned long long)fkey(v.z) << 14) | (unsigned long long)(16383 - (base + 2)); }
            if (v.w >= THRF) { c++; int p = atomicAdd(&s_ncand, 1); if (p < CAP)
                s_cand[p] = ((unsigned long long)fkey(v.w) << 14) | (unsigned long long)(16383 - (base + 3)); }
        }
    }
    {
        unsigned int ws = __reduce_add_sync(0xffffffffu, (unsigned int)c);
        if (lane == 0) s_wcnt[0][wid] = (int)ws;
    }
    __syncthreads();
    int tot = 0;
#pragma unroll
    for (int w = 0; w < 16; w++)
        tot += s_wcnt[0][w];

    int C;
    if (tot >= TK && tot <= CAP) {
        C = tot;                         // fast path (always taken for N(0,1) data)
    } else {
        // ---------- fallback: exact binary-search cutoff, re-reading cls ----------
        __syncthreads();
        unsigned int T = 0;
        for (int bit = 10; bit >= 0; bit--) {
            unsigned int candT = T | (1u << bit);
            unsigned int Tsh = candT << 21;
            int cc = 0;
            for (int i = t; i < AN; i += NT)
                cc += (fkey(__ldg(&((const float*)cb4)[i])) >= Tsh);
            unsigned int ws = __reduce_add_sync(0xffffffffu, (unsigned int)cc);
            int buf = bit & 1;
            if (lane == 0) s_wcnt[buf][wid] = (int)ws;
            __syncthreads();
            int tt = 0;
#pragma unroll
            for (int w = 0; w < 16; w++)
                tt += s_wcnt[buf][w];
            if (tt >= TK) T = candT;
            __syncthreads();
        }
        unsigned int cut = T << 21;
        if (cut == 0) cut = 1;
        if (t == 0) s_ncand = 0;
        __syncthreads();
        for (int i = t; i < AN; i += NT) {
            unsigned int k = fkey(__ldg(&((const float*)cb4)[i]));
            if (k >= cut) {
                int p = atomicAdd(&s_ncand, 1);
                if (p < CAP)
                    s_cand[p] = ((unsigned long long)k << 14) |
                                (unsigned long long)(16383 - i);
            }
        }
        __syncthreads();
        C = s_ncand;
        if (C > CAP) C = CAP;
    }
    __syncthreads();

    // ---------------- Phase 2: exact ranking -> top-60 keys ----------------
    for (int cc2 = t; cc2 < C; cc2 += NT) {
        unsigned long long k = s_cand[cc2];
        int r = 0;
#pragma unroll 4
        for (int m = 0; m < C; m++)
            r += (s_cand[m] > k);
        if (r < TK) s_key[r] = k;
    }
    __syncthreads();

    // ---------------- Phase 3: scores + validity ----------------
    float sc = 0.0f;
    if (t < TK) {
        unsigned long long k = s_key[t];
        float logit = fkey_inv((unsigned int)(k >> 14));
        sc = 1.0f / (1.0f + expf(-logit));
        s_sc[t] = sc;
    }
    {
        unsigned int vb = __ballot_sync(0xffffffffu, (t < TK) && (sc > 0.15f));
        if (wid < 2 && lane == 0) s_valid[wid] = vb;
    }
    __syncthreads();

    unsigned long long valid = ((unsigned long long)s_valid[1] << 32) | s_valid[0];
    int nc = __popcll(valid);
    if (nc > NMSK) nc = NMSK;

    // cand rows = first nc valid rows in rank order (fast path: rows 0..19)
    if (t < TK) {
        if ((valid >> t) & 1ull) {
            int rv = __popcll(valid & ((1ull << t) - 1ull));
            if (rv < NMSK) s_crow[rv] = t;
        }
    }
    __syncthreads();

    // ---------------- Phase 4: gather off/shp for cand rows (<=120 loads) ----------------
    if (t < 6 * NMSK) {
        int ci = t / 6, comp = t - ci * 6;
        if (ci < nc) {
            int idx = 16383 - (int)(s_key[s_crow[ci]] & 16383ull);
            size_t base = (size_t)b * 3 * AN;
            const float* src = (comp < 3) ? (off + base + (size_t)comp * AN)
                                          : (shp + base + (size_t)(comp - 3) * AN);
            s_gv[comp][ci] = __ldg(&src[idx]);
        }
    }
    __syncthreads();

    // ---------------- Phase 5: box build for cand rows ----------------
    if (t < nc) {
        int idx = 16383 - (int)(s_key[s_crow[t]] & 16383ull);
        int z   = idx / 576;
        int rem = idx - z * 576;
        int y   = rem / 24;
        int x   = rem - y * 24;
        float cz = ((float)z + s_gv[0][t]) * 4.0f;   // stride = 96/24 = 4
        float cy = ((float)y + s_gv[1][t]) * 4.0f;
        float cx = ((float)x + s_gv[2][t]) * 4.0f;
        float dz = 2.0f * s_gv[3][t];
        float dy = 2.0f * s_gv[4][t];
        float dx = 2.0f * s_gv[5][t];
        s_ctr[t][0] = cz; s_ctr[t][1] = cy; s_ctr[t][2] = cx;
        s_sz[t][0] = dz;  s_sz[t][1] = dy;  s_sz[t][2] = dx;
        s_lo[t][0] = cz - dz * 0.5f; s_lo[t][1] = cy - dy * 0.5f; s_lo[t][2] = cx - dx * 0.5f;
        s_hi[t][0] = cz + dz * 0.5f; s_hi[t][1] = cy + dy * 0.5f; s_hi[t][2] = cx + dx * 0.5f;
        s_vol[t] = dz * dy * dx;
    }
    __syncthreads();

    // ---------------- Phase 6: IoU bitmask among cand rows (<=20x20) ----------------
    if (t < nc) {
        float l0 = s_lo[t][0], l1 = s_lo[t][1], l2 = s_lo[t][2];
        float h0 = s_hi[t][0], h1 = s_hi[t][1], h2 = s_hi[t][2];
        float vi = s_vol[t];
        unsigned int m = 0;
        for (int j = 0; j < nc; j++) {
            float iz = fminf(h0, s_hi[j][0]) - fmaxf(l0, s_lo[j][0]);
            float iy = fminf(h1, s_hi[j][1]) - fmaxf(l1, s_lo[j][1]);
            float ix = fminf(h2, s_hi[j][2]) - fmaxf(l2, s_lo[j][2]);
            float inter = fmaxf(iz, 0.0f) * fmaxf(iy, 0.0f) * fmaxf(ix, 0.0f);
            float uni = vi + s_vol[j] - inter;
            float iou = inter / fmaxf(uni, 1e-8f);
            unsigned int hit = (iou > 0.05f) && (j != t);
            m |= hit << j;
        }
        s_m[t] = m;
    }
    __syncthreads();

    // ---------------- Phase 7: serial bitmask NMS over cand rows ----------------
    if (t == 0) {
        unsigned int supp = 0, kept = 0;
#pragma unroll
        for (int ci = 0; ci < NMSK; ci++) {
            if (ci < nc) {
                unsigned int keep = !((supp >> ci) & 1u);
                kept |= keep << ci;
                if (keep) supp |= s_m[ci];
            }
        }
        s_kept = kept;
    }
    __syncthreads();

    // ---------------- Phase 8: output (kept in rank order, -1 padding) ----------------
    float* ob = out + (size_t)b * TK * 8;
    if (t < TK) {
        unsigned int kept = s_kept;
        int nk = __popc(kept);
        if (t < nk) {
            // t-th set bit of kept
            int ci = 0, c2 = t;
#pragma unroll
            for (int q = 0; q < NMSK; q++) {
                if ((kept >> q) & 1u) {
                    if (c2 == 0) { ci = q; }
                    c2--;
                }
            }
            float4* o4 = (float4*)(ob + t * 8);
            o4[0] = make_float4(1.0f, s_sc[s_crow[ci]], s_ctr[ci][0], s_ctr[ci][1]);
            o4[1] = make_float4(s_ctr[ci][2], s_sz[ci][0], s_sz[ci][1], s_sz[ci][2]);
        } else {
            float4* o4 = (float4*)(ob + t * 8);
            o4[0] = make_float4(-1.0f, -1.0f, -1.0f, -1.0f);
            o4[1] = make_float4(-1.0f, -1.0f, -1.0f, -1.0f);
        }
    }
}

extern "C" void kernel_launch(void* const* d_in, const int* in_sizes, int n_in,
                              void* d_out, int out_size)
{
    const float* cls = (const float*)d_in[0];
    const float* shp = (const float*)d_in[1];
    const float* off = (const float*)d_in[2];
    float* out = (float*)d_out;
    detect_fused_kernel<<<NB, NT>>>(cls, shp, off, out);
}

// round 13
// speedup vs baseline: 1.8190x; 1.0037x over previous
#include <cuda_runtime.h>
#include <cstdint>

#define AN 13824          // 24*24*24 anchors
#define NT 512            // threads per block
#define NV 3456           // AN/4 float4s
#define TK 60             // TOPK
#define NMSK 20           // NMS_TOPK
#define CAP 512           // candidate capacity
#define NB 256            // batches
#define THRF 2.25f        // fast-path threshold: count ~169+-13, >=60 at 8 sigma

__device__ __forceinline__ unsigned int fkey(float x) {
    unsigned int b = __float_as_uint(x);
    return (b & 0x80000000u) ? ~b : (b | 0x80000000u);
}
__device__ __forceinline__ float fkey_inv(unsigned int u) {
    unsigned int b = (u & 0x80000000u) ? (u & 0x7fffffffu) : ~u;
    return __uint_as_float(b);
}

__global__ __launch_bounds__(NT, 2)
void detect_fused_kernel(const float* __restrict__ cls,
                         const float* __restrict__ shp,
                         const float* __restrict__ off,
                         float* __restrict__ out)
{
    const int b    = blockIdx.x;
    const int t    = threadIdx.x;
    const int lane = t & 31;
    const int wid  = t >> 5;

    __shared__ unsigned long long s_cand[CAP];
    __shared__ int   s_ncand;
    __shared__ int   s_wcnt[2][16];
    __shared__ unsigned long long s_key[TK];
    __shared__ float s_sc[TK];
    __shared__ unsigned int s_valid[2];
    __shared__ int   s_crow[NMSK];
    __shared__ int   s_nc;
    __shared__ float s_gv[6][NMSK];
    __shared__ float s_ctr[NMSK][3], s_sz[NMSK][3];
    __shared__ float s_lo[NMSK][3], s_hi[NMSK][3], s_vol[NMSK];
    __shared__ unsigned int s_m[NMSK];
    __shared__ unsigned int s_kept;

    if (t == 0) s_ncand = 0;
    __syncthreads();

    // ---------------- Phase 1a: issue ALL loads first (no consumption between) ----------------
    const float4* cb4 = (const float4*)(cls + (size_t)b * AN);
    const int i6  = t + NT * 6;
    const int i6c = (i6 < NV) ? i6 : (NV - 1);   // clamp tail load (result discarded)
    float4 v0 = __ldg(&cb4[t + NT * 0]);
    float4 v1 = __ldg(&cb4[t + NT * 1]);
    float4 v2 = __ldg(&cb4[t + NT * 2]);
    float4 v3 = __ldg(&cb4[t + NT * 3]);
    float4 v4 = __ldg(&cb4[t + NT * 4]);
    float4 v5 = __ldg(&cb4[t + NT * 5]);
    float4 v6 = __ldg(&cb4[i6c]);
    const bool has6 = (i6 < NV);

    // ---------------- Phase 1b: count + collect qualifiers ----------------
    int c = 0;
#define PUSH1(val, idx) \
    if ((val) >= THRF) { c++; int p = atomicAdd(&s_ncand, 1); if (p < CAP) \
        s_cand[p] = ((unsigned long long)fkey(val) << 14) | (unsigned long long)(16383 - (idx)); }
#define PUSH4(v, base) \
    PUSH1((v).x, (base) + 0); PUSH1((v).y, (base) + 1); \
    PUSH1((v).z, (base) + 2); PUSH1((v).w, (base) + 3);

    PUSH4(v0, 4 * (t + NT * 0));
    PUSH4(v1, 4 * (t + NT * 1));
    PUSH4(v2, 4 * (t + NT * 2));
    PUSH4(v3, 4 * (t + NT * 3));
    PUSH4(v4, 4 * (t + NT * 4));
    PUSH4(v5, 4 * (t + NT * 5));
    if (has6) { PUSH4(v6, 4 * i6); }
#undef PUSH4
#undef PUSH1

    {
        unsigned int ws = __reduce_add_sync(0xffffffffu, (unsigned int)c);
        if (lane == 0) s_wcnt[0][wid] = (int)ws;
    }
    __syncthreads();
    int tot = 0;
#pragma unroll
    for (int w = 0; w < 16; w++)
        tot += s_wcnt[0][w];

    if (tot >= TK && tot <= CAP) {
        // ================= FAST PATH (always taken for N(0,1) data) =================
        // All top-60 scores are sigmoid(>=2.25) > 0.15 => all valid => cand = top-20.
        int C = tot;
        // exact ranking -> top-20 keys only
        for (int cc2 = t; cc2 < C; cc2 += NT) {
            unsigned long long k = s_cand[cc2];
            int r = 0;
#pragma unroll 4
            for (int m = 0; m < C; m++)
                r += (s_cand[m] > k);
            if (r < NMSK) s_key[r] = k;
        }
        if (t == 0) s_nc = NMSK;
        if (t < NMSK) s_crow[t] = t;
        __syncthreads();
        if (t < NMSK) {
            float logit = fkey_inv((unsigned int)(s_key[t] >> 14));
            s_sc[t] = 1.0f / (1.0f + expf(-logit));
        }
        __syncthreads();
    } else {
        // ================= FALLBACK (exact, never taken for this data) =================
        unsigned int T = 0;
        for (int bit = 10; bit >= 0; bit--) {
            unsigned int candT = T | (1u << bit);
            unsigned int Tsh = candT << 21;
            int cc = 0;
            for (int i = t; i < AN; i += NT)
                cc += (fkey(__ldg(&((const float*)cb4)[i])) >= Tsh);
            unsigned int ws = __reduce_add_sync(0xffffffffu, (unsigned int)cc);
            int buf = bit & 1;
            if (lane == 0) s_wcnt[buf][wid] = (int)ws;
            __syncthreads();
            int tt = 0;
#pragma unroll
            for (int w = 0; w < 16; w++)
                tt += s_wcnt[buf][w];
            if (tt >= TK) T = candT;
            __syncthreads();
        }
        unsigned int cut = T << 21;
        if (cut == 0) cut = 1;
        if (t == 0) s_ncand = 0;
        __syncthreads();
        for (int i = t; i < AN; i += NT) {
            unsigned int k = fkey(__ldg(&((const float*)cb4)[i]));
            if (k >= cut) {
                int p = atomicAdd(&s_ncand, 1);
                if (p < CAP)
                    s_cand[p] = ((unsigned long long)k << 14) |
                                (unsigned long long)(16383 - i);
            }
        }
        __syncthreads();
        int C = s_ncand;
        if (C > CAP) C = CAP;
        // full top-60 ranking
        for (int cc2 = t; cc2 < C; cc2 += NT) {
            unsigned long long k = s_cand[cc2];
            int r = 0;
            for (int m = 0; m < C; m++)
                r += (s_cand[m] > k);
            if (r < TK) s_key[r] = k;
        }
        __syncthreads();
        float sc = 0.0f;
        if (t < TK) {
            float logit = fkey_inv((unsigned int)(s_key[t] >> 14));
            sc = 1.0f / (1.0f + expf(-logit));
            s_sc[t] = sc;
        }
        {
            unsigned int vb = __ballot_sync(0xffffffffu, (t < TK) && (sc > 0.15f));
            if (wid < 2 && lane == 0) s_valid[wid] = vb;
        }
        __syncthreads();
        unsigned long long valid = ((unsigned long long)s_valid[1] << 32) | s_valid[0];
        int nc = __popcll(valid);
        if (nc > NMSK) nc = NMSK;
        if (t == 0) s_nc = nc;
        if (t < TK) {
            if ((valid >> t) & 1ull) {
                int rv = __popcll(valid & ((1ull << t) - 1ull));
                if (rv < NMSK) s_crow[rv] = t;
            }
        }
        __syncthreads();
    }

    const int nc = s_nc;

    // ---------------- Phase 4: gather off/shp for cand rows (<=120 loads) ----------------
    if (t < 6 * NMSK) {
        int ci = t / 6, comp = t - ci * 6;
        if (ci < nc) {
            int idx = 16383 - (int)(s_key[s_crow[ci]] & 16383ull);
            size_t base = (size_t)b * 3 * AN;
            const float* src = (comp < 3) ? (off + base + (size_t)comp * AN)
                                          : (shp + base + (size_t)(comp - 3) * AN);
            s_gv[comp][ci] = __ldg(&src[idx]);
        }
    }
    __syncthreads();

    // ---------------- Phase 5: box build for cand rows ----------------
    if (t < nc) {
        int idx = 16383 - (int)(s_key[s_crow[t]] & 16383ull);
        int z   = idx / 576;
        int rem = idx - z * 576;
        int y   = rem / 24;
        int x   = rem - y * 24;
        float cz = ((float)z + s_gv[0][t]) * 4.0f;   // stride = 96/24 = 4
        float cy = ((float)y + s_gv[1][t]) * 4.0f;
        float cx = ((float)x + s_gv[2][t]) * 4.0f;
        float dz = 2.0f * s_gv[3][t];
        float dy = 2.0f * s_gv[4][t];
        float dx = 2.0f * s_gv[5][t];
        s_ctr[t][0] = cz; s_ctr[t][1] = cy; s_ctr[t][2] = cx;
        s_sz[t][0] = dz;  s_sz[t][1] = dy;  s_sz[t][2] = dx;
        s_lo[t][0] = cz - dz * 0.5f; s_lo[t][1] = cy - dy * 0.5f; s_lo[t][2] = cx - dx * 0.5f;
        s_hi[t][0] = cz + dz * 0.5f; s_hi[t][1] = cy + dy * 0.5f; s_hi[t][2] = cx + dx * 0.5f;
        s_vol[t] = dz * dy * dx;
    }
    __syncthreads();

    // ---------------- Phase 6: IoU bitmask among cand rows (<=20x20) ----------------
    if (t < nc) {
        float l0 = s_lo[t][0], l1 = s_lo[t][1], l2 = s_lo[t][2];
        float h0 = s_hi[t][0], h1 = s_hi[t][1], h2 = s_hi[t][2];
        float vi = s_vol[t];
        unsigned int m = 0;
        for (int j = 0; j < nc; j++) {
            float iz = fminf(h0, s_hi[j][0]) - fmaxf(l0, s_lo[j][0]);
            float iy = fminf(h1, s_hi[j][1]) - fmaxf(l1, s_lo[j][1]);
            float ix = fminf(h2, s_hi[j][2]) - fmaxf(l2, s_lo[j][2]);
            float inter = fmaxf(iz, 0.0f) * fmaxf(iy, 0.0f) * fmaxf(ix, 0.0f);
            float uni = vi + s_vol[j] - inter;
            float iou = inter / fmaxf(uni, 1e-8f);
            unsigned int hit = (iou > 0.05f) && (j != t);
            m |= hit << j;
        }
        s_m[t] = m;
    }
    __syncthreads();

    // ---------------- Phase 7: serial bitmask NMS over cand rows ----------------
    if (t == 0) {
        unsigned int supp = 0, kept = 0;
#pragma unroll
        for (int ci = 0; ci < NMSK; ci++) {
            if (ci < nc) {
                unsigned int keep = !((supp >> ci) & 1u);
                kept |= keep << ci;
                if (keep) supp |= s_m[ci];
            }
        }
        s_kept = kept;
    }
    __syncthreads();

    // ---------------- Phase 8: output (kept in rank order, -1 padding) ----------------
    float* ob = out + (size_t)b * TK * 8;
    if (t < TK) {
        unsigned int kept = s_kept;
        int nk = __popc(kept);
        if (t < nk) {
            // t-th set bit of kept
            int ci = 0, c2 = t;
#pragma unroll
            for (int q = 0; q < NMSK; q++) {
                if ((kept >> q) & 1u) {
                    if (c2 == 0) { ci = q; }
                    c2--;
                }
            }
            float4* o4 = (float4*)(ob + t * 8);
            o4[0] = make_float4(1.0f, s_sc[s_crow[ci]], s_ctr[ci][0], s_ctr[ci][1]);
            o4[1] = make_float4(s_ctr[ci][2], s_sz[ci][0], s_sz[ci][1], s_sz[ci][2]);
        } else {
            float4* o4 = (float4*)(ob + t * 8);
            o4[0] = make_float4(-1.0f, -1.0f, -1.0f, -1.0f);
            o4[1] = make_float4(-1.0f, -1.0f, -1.0f, -1.0f);
        }
    }
}

extern "C" void kernel_launch(void* const* d_in, const int* in_sizes, int n_in,
                              void* d_out, int out_size)
{
    const float* cls = (const float*)d_in[0];
    const float* shp = (const float*)d_in[1];
    const float* off = (const float*)d_in[2];
    float* out = (float*)d_out;
    detect_fused_kernel<<<NB, NT>>>(cls, shp, off, out);
}

// round 14
// speedup vs baseline: 1.8466x; 1.0152x over previous
#include <cuda_runtime.h>
#include <cstdint>

#define AN 13824          // 24*24*24 anchors
#define NT 512            // threads per block
#define NV 3456           // AN/4 float4s
#define TK 60             // TOPK
#define NMSK 20           // NMS_TOPK
#define SEGSZ 48          // per-warp segment capacity (mean 10.5, sigma 3.2 -> 11 sigma)
#define NWARP 16
#define CAP (SEGSZ * NWARP)   // 768
#define NB 256            // batches
#define THRF 2.25f        // fast-path threshold: ~169+-13 qualifiers per batch

__device__ __forceinline__ unsigned int fkey(float x) {
    unsigned int b = __float_as_uint(x);
    return (b & 0x80000000u) ? ~b : (b | 0x80000000u);
}
__device__ __forceinline__ float fkey_inv(unsigned int u) {
    unsigned int b = (u & 0x80000000u) ? (u & 0x7fffffffu) : ~u;
    return __uint_as_float(b);
}

__global__ __launch_bounds__(NT, 2)
void detect_fused_kernel(const float* __restrict__ cls,
                         const float* __restrict__ shp,
                         const float* __restrict__ off,
                         float* __restrict__ out)
{
    const int b    = blockIdx.x;
    const int t    = threadIdx.x;
    const int lane = t & 31;
    const int wid  = t >> 5;
    const unsigned int ltmask = (1u << lane) - 1u;

    __shared__ unsigned long long s_seg[NWARP][SEGSZ];
    __shared__ unsigned long long s_cand[CAP];
    __shared__ int   s_segcnt[NWARP];
    __shared__ int   s_segoff[NWARP];
    __shared__ int   s_tot, s_maxseg;
    __shared__ int   s_wcnt[2][16];
    __shared__ int   s_ncand;
    __shared__ unsigned long long s_key[TK];
    __shared__ float s_sc[TK];
    __shared__ unsigned int s_valid[2];
    __shared__ int   s_crow[NMSK];
    __shared__ int   s_nc;
    __shared__ float s_gv[6][NMSK];
    __shared__ float s_ctr[NMSK][3], s_sz[NMSK][3];
    __shared__ float s_lo[NMSK][3], s_hi[NMSK][3], s_vol[NMSK];
    __shared__ unsigned int s_m[NMSK];
    __shared__ unsigned int s_kept;

    // ---------------- Phase 1a: issue ALL loads first ----------------
    const float4* cb4 = (const float4*)(cls + (size_t)b * AN);
    const int i6  = t + NT * 6;
    const int i6c = (i6 < NV) ? i6 : (NV - 1);   // clamp tail load
    float4 v0 = __ldg(&cb4[t + NT * 0]);
    float4 v1 = __ldg(&cb4[t + NT * 1]);
    float4 v2 = __ldg(&cb4[t + NT * 2]);
    float4 v3 = __ldg(&cb4[t + NT * 3]);
    float4 v4 = __ldg(&cb4[t + NT * 4]);
    float4 v5 = __ldg(&cb4[t + NT * 5]);
    float4 v6 = __ldg(&cb4[i6c]);
    if (i6 >= NV) { v6.x = v6.y = v6.z = v6.w = -1e30f; }  // never qualifies

    // ---------------- Phase 1b: atomic-free push into per-warp segment ----------------
    int wcnt = 0;
#define PUSHC(val, idx) \
    { unsigned int mm = __ballot_sync(0xffffffffu, (val) >= THRF); \
      if (mm) { \
        if ((val) >= THRF) { \
            int pos = wcnt + __popc(mm & ltmask); \
            if (pos < SEGSZ) \
                s_seg[wid][pos] = ((unsigned long long)fkey(val) << 14) | \
                                  (unsigned long long)(16383 - (idx)); \
        } \
        wcnt += __popc(mm); \
      } }
#define PUSH4(v, base) \
    PUSHC((v).x, (base) + 0); PUSHC((v).y, (base) + 1); \
    PUSHC((v).z, (base) + 2); PUSHC((v).w, (base) + 3);

    PUSH4(v0, 4 * (t + NT * 0));
    PUSH4(v1, 4 * (t + NT * 1));
    PUSH4(v2, 4 * (t + NT * 2));
    PUSH4(v3, 4 * (t + NT * 3));
    PUSH4(v4, 4 * (t + NT * 4));
    PUSH4(v5, 4 * (t + NT * 5));
    PUSH4(v6, 4 * i6);
#undef PUSH4
#undef PUSHC

    if (lane == 0) s_segcnt[wid] = wcnt;
    __syncthreads();

    // warp 0: prefix over 16 segment counts
    if (wid == 0) {
        int cnt = (lane < NWARP) ? s_segcnt[lane] : 0;
        int incl = cnt;
#pragma unroll
        for (int o = 1; o < 16; o <<= 1) {
            int v = __shfl_up_sync(0xffffffffu, incl, o);
            if (lane >= o) incl += v;
        }
        if (lane < NWARP) s_segoff[lane] = incl - cnt;
        int mx = __reduce_max_sync(0xffffffffu, (lane < NWARP) ? cnt : 0);
        int tt = __shfl_sync(0xffffffffu, incl, NWARP - 1);
        if (lane == 0) { s_tot = tt; s_maxseg = mx; }
    }
    __syncthreads();

    const int tot = s_tot;

    if (tot >= TK && tot <= CAP && s_maxseg <= SEGSZ) {
        // ================= FAST PATH (always taken for N(0,1) data) =================
        // compact segments -> contiguous s_cand
        {
            int n = (wcnt < SEGSZ) ? wcnt : SEGSZ;
            int base = s_segoff[wid];
            for (int p = lane; p < n; p += 32)
                s_cand[base + p] = s_seg[wid][p];
        }
        __syncthreads();
        // exact ranking -> top-20 keys (all top-60 valid: sigmoid(>=2.25) > 0.15)
        int C = tot;
        for (int cc2 = t; cc2 < C; cc2 += NT) {
            unsigned long long k = s_cand[cc2];
            int r = 0;
#pragma unroll 4
            for (int m = 0; m < C; m++)
                r += (s_cand[m] > k);
            if (r < NMSK) s_key[r] = k;
        }
        if (t == 0) s_nc = NMSK;
        if (t < NMSK) s_crow[t] = t;
        __syncthreads();
        if (t < NMSK) {
            float logit = fkey_inv((unsigned int)(s_key[t] >> 14));
            s_sc[t] = 1.0f / (1.0f + expf(-logit));
        }
        __syncthreads();
    } else {
        // ================= FALLBACK (exact, never taken for this data) =================
        unsigned int T = 0;
        for (int bit = 10; bit >= 0; bit--) {
            unsigned int candT = T | (1u << bit);
            unsigned int Tsh = candT << 21;
            int cc = 0;
            for (int i = t; i < AN; i += NT)
                cc += (fkey(__ldg(&((const float*)cb4)[i])) >= Tsh);
            unsigned int ws = __reduce_add_sync(0xffffffffu, (unsigned int)cc);
            int buf = bit & 1;
            if (lane == 0) s_wcnt[buf][wid] = (int)ws;
            __syncthreads();
            int tt = 0;
#pragma unroll
            for (int w = 0; w < 16; w++)
                tt += s_wcnt[buf][w];
            if (tt >= TK) T = candT;
            __syncthreads();
        }
        unsigned int cut = T << 21;
        if (cut == 0) cut = 1;
        if (t == 0) s_ncand = 0;
        __syncthreads();
        for (int i = t; i < AN; i += NT) {
            unsigned int k = fkey(__ldg(&((const float*)cb4)[i]));
            if (k >= cut) {
                int p = atomicAdd(&s_ncand, 1);
                if (p < CAP)
                    s_cand[p] = ((unsigned long long)k << 14) |
                                (unsigned long long)(16383 - i);
            }
        }
        __syncthreads();
        int C = s_ncand;
        if (C > CAP) C = CAP;
        for (int cc2 = t; cc2 < C; cc2 += NT) {
            unsigned long long k = s_cand[cc2];
            int r = 0;
            for (int m = 0; m < C; m++)
                r += (s_cand[m] > k);
            if (r < TK) s_key[r] = k;
        }
        __syncthreads();
        float sc = 0.0f;
        if (t < TK) {
            float logit = fkey_inv((unsigned int)(s_key[t] >> 14));
            sc = 1.0f / (1.0f + expf(-logit));
            s_sc[t] = sc;
        }
        {
            unsigned int vb = __ballot_sync(0xffffffffu, (t < TK) && (sc > 0.15f));
            if (wid < 2 && lane == 0) s_valid[wid] = vb;
        }
        __syncthreads();
        unsigned long long valid = ((unsigned long long)s_valid[1] << 32) | s_valid[0];
        int nc = __popcll(valid);
        if (nc > NMSK) nc = NMSK;
        if (t == 0) s_nc = nc;
        if (t < TK) {
            if ((valid >> t) & 1ull) {
                int rv = __popcll(valid & ((1ull << t) - 1ull));
                if (rv < NMSK) s_crow[rv] = t;
            }
        }
        __syncthreads();
    }

    const int nc = s_nc;

    // ---------------- Phase 4: gather off/shp for cand rows (<=120 loads) ----------------
    if (t < 6 * NMSK) {
        int ci = t / 6, comp = t - ci * 6;
        if (ci < nc) {
            int idx = 16383 - (int)(s_key[s_crow[ci]] & 16383ull);
            size_t base = (size_t)b * 3 * AN;
            const float* src = (comp < 3) ? (off + base + (size_t)comp * AN)
                                          : (shp + base + (size_t)(comp - 3) * AN);
            s_gv[comp][ci] = __ldg(&src[idx]);
        }
    }
    __syncthreads();

    // ---------------- Phase 5: box build for cand rows ----------------
    if (t < nc) {
        int idx = 16383 - (int)(s_key[s_crow[t]] & 16383ull);
        int z   = idx / 576;
        int rem = idx - z * 576;
        int y   = rem / 24;
        int x   = rem - y * 24;
        float cz = ((float)z + s_gv[0][t]) * 4.0f;   // stride = 96/24 = 4
        float cy = ((float)y + s_gv[1][t]) * 4.0f;
        float cx = ((float)x + s_gv[2][t]) * 4.0f;
        float dz = 2.0f * s_gv[3][t];
        float dy = 2.0f * s_gv[4][t];
        float dx = 2.0f * s_gv[5][t];
        s_ctr[t][0] = cz; s_ctr[t][1] = cy; s_ctr[t][2] = cx;
        s_sz[t][0] = dz;  s_sz[t][1] = dy;  s_sz[t][2] = dx;
        s_lo[t][0] = cz - dz * 0.5f; s_lo[t][1] = cy - dy * 0.5f; s_lo[t][2] = cx - dx * 0.5f;
        s_hi[t][0] = cz + dz * 0.5f; s_hi[t][1] = cy + dy * 0.5f; s_hi[t][2] = cx + dx * 0.5f;
        s_vol[t] = dz * dy * dx;
    }
    __syncthreads();

    // ---------------- Phase 6: IoU bitmask among cand rows (<=20x20) ----------------
    if (t < nc) {
        float l0 = s_lo[t][0], l1 = s_lo[t][1], l2 = s_lo[t][2];
        float h0 = s_hi[t][0], h1 = s_hi[t][1], h2 = s_hi[t][2];
        float vi = s_vol[t];
        unsigned int m = 0;
        for (int j = 0; j < nc; j++) {
            float iz = fminf(h0, s_hi[j][0]) - fmaxf(l0, s_lo[j][0]);
            float iy = fminf(h1, s_hi[j][1]) - fmaxf(l1, s_lo[j][1]);
            float ix = fminf(h2, s_hi[j][2]) - fmaxf(l2, s_lo[j][2]);
            float inter = fmaxf(iz, 0.0f) * fmaxf(iy, 0.0f) * fmaxf(ix, 0.0f);
            float uni = vi + s_vol[j] - inter;
            float iou = inter / fmaxf(uni, 1e-8f);
            unsigned int hit = (iou > 0.05f) && (j != t);
            m |= hit << j;
        }
        s_m[t] = m;
    }
    __syncthreads();

    // ---------------- Phase 7: serial bitmask NMS over cand rows ----------------
    if (t == 0) {
        unsigned int supp = 0, kept = 0;
#pragma unroll
        for (int ci = 0; ci < NMSK; ci++) {
            if (ci < nc) {
                unsigned int keep = !((supp >> ci) & 1u);
                kept |= keep << ci;
                if (keep) supp |= s_m[ci];
            }
        }
        s_kept = kept;
    }
    __syncthreads();

    // ---------------- Phase 8: output (kept in rank order, -1 padding) ----------------
    float* ob = out + (size_t)b * TK * 8;
    if (t < TK) {
        unsigned int kept = s_kept;
        int nk = __popc(kept);
        if (t < nk) {
            int ci = 0, c2 = t;
#pragma unroll
            for (int q = 0; q < NMSK; q++) {
                if ((kept >> q) & 1u) {
                    if (c2 == 0) { ci = q; }
                    c2--;
                }
            }
            float4* o4 = (float4*)(ob + t * 8);
            o4[0] = make_float4(1.0f, s_sc[s_crow[ci]], s_ctr[ci][0], s_ctr[ci][1]);
            o4[1] = make_float4(s_ctr[ci][2], s_sz[ci][0], s_sz[ci][1], s_sz[ci][2]);
        } else {
            float4* o4 = (float4*)(ob + t * 8);
            o4[0] = make_float4(-1.0f, -1.0f, -1.0f, -1.0f);
            o4[1] = make_float4(-1.0f, -1.0f, -1.0f, -1.0f);
        }
    }
}

extern "C" void kernel_launch(void* const* d_in, const int* in_sizes, int n_in,
                              void* d_out, int out_size)
{
    const float* cls = (const float*)d_in[0];
    const float* shp = (const float*)d_in[1];
    const float* off = (const float*)d_in[2];
    float* out = (float*)d_out;
    detect_fused_kernel<<<NB, NT>>>(cls, shp, off, out);
}